// round 3
// baseline (speedup 1.0000x reference)
#include <cuda_runtime.h>
#include <cuda_bf16.h>

#define RDIM     256
#define NPIX     32768            // 8*64*64
#define THREADS  512
#define SV_FLOATS NPIX            // staged values (no padding needed: all accesses conflict-free)
#define SMEM_FLOATS (SV_FLOATS + 48)
#define SMEM_BYTES  (SMEM_FLOATS * 4)

__device__ __forceinline__ float softplusf(float x) {
    // numerically stable softplus: max(x,0) + log1p(exp(-|x|))
    return fmaxf(x, 0.f) + log1pf(__expf(-fabsf(x)));
}

__global__ void __launch_bounds__(THREADS, 1)
mvnd_kernel(const float* __restrict__ rep,
            const float* __restrict__ mW, const float* __restrict__ mb,
            const float* __restrict__ sW, const float* __restrict__ sb,
            float* __restrict__ out)
{
    extern __shared__ float smem[];
    float* sv   = smem;                 // [NPIX] staged unnormalized probs
    float* sraw = smem + SV_FLOATS;     // [9]  GEMV dots
    float* sred = sraw + 9;             // [16] warp partial sums
    float* scst = sred + 16;            // [12] derived constants

    const int tid  = threadIdx.x;
    const int lane = tid & 31;
    const int w    = tid >> 5;
    const int n    = blockIdx.x;

    // ---------------- Phase 0: 9x256 GEMV (3 mean rows + 6 scale rows) ----------------
    if (w < 9) {
        const float* rp = rep + (size_t)n * RDIM + lane;
        const float* wp = ((w < 3) ? (mW + w * RDIM) : (sW + (w - 3) * RDIM)) + lane;
        float acc = 0.f;
        #pragma unroll
        for (int j = 0; j < 8; j++) acc = fmaf(rp[32 * j], wp[32 * j], acc);
        #pragma unroll
        for (int o = 16; o; o >>= 1) acc += __shfl_xor_sync(0xffffffffu, acc, o);
        if (lane == 0) sraw[w] = acc;
    }
    __syncthreads();

    if (tid == 0) {
        const float mx = sraw[0] + mb[0];
        const float my = sraw[1] + mb[1];
        const float mz = sraw[2] + mb[2];
        const float s0 = softplusf(sraw[3] + sb[0]) + 1e-6f;
        const float s1 = softplusf(sraw[4] + sb[1]) + 1e-6f;
        const float s2 = softplusf(sraw[5] + sb[2]) + 1e-6f;
        const float s3 = softplusf(sraw[6] + sb[3]) + 1e-6f;
        const float s4 = softplusf(sraw[7] + sb[4]) + 1e-6f;
        const float s5 = softplusf(sraw[8] + sb[5]) + 1e-6f;
        const float L00 = softplusf(s0);
        const float L10 = s1;
        const float L11 = softplusf(s2);
        const float L20 = s3;
        const float L21 = s4;
        const float L22 = softplusf(s5);
        scst[0] = mx;
        scst[1] = my;
        scst[2] = mz;
        scst[3] = 1.f / L00;
        scst[4] = 1.f / L11;
        scst[5] = 1.f / L22;
        scst[6] = L10;
        scst[7] = L20;
        scst[8] = L21 / L22;   // t21
    }
    __syncthreads();

    const float mx  = scst[0], my = scst[1], mz = scst[2];
    const float i00 = scst[3], i11 = scst[4], i22 = scst[5];
    const float L10 = scst[6], L20 = scst[7], t21 = scst[8];

    // ---------------- Phase 1: compute exp(-0.5*maha), stage in smem ----------------
    // pixel i = tid + 512*k :  x = tid&63 (fixed),  y = (tid>>6) + 8*(k&7),  z = k>>3
    const float xf = (float)(tid & 63) - 31.5f;
    const float y0 = (xf - mx) * i00;
    const float y0sq = y0 * y0;
    const float d1 = (my + L10 * y0) * i11;     // y1 = yf*i11 - d1
    const float e2 = (mz + L20 * y0) * i22;     // y2 = zf*i22 - e2 - t21*y1
    const float yb = (float)(tid >> 6) - 31.5f;

    float m01[8], w1[8];
    #pragma unroll
    for (int kk = 0; kk < 8; kk++) {
        const float yf = yb + 8.f * (float)kk;
        const float y1 = fmaf(yf, i11, -d1);
        m01[kk] = fmaf(y1, y1, y0sq);           // y0^2 + y1^2
        w1[kk]  = t21 * y1;
    }

    float sum = 0.f;
    int idx = tid;
    #pragma unroll
    for (int z = 0; z < 8; z++) {
        const float zc = fmaf((float)z - 3.5f, i22, -e2);   // zf*i22 - e2
        #pragma unroll
        for (int kk = 0; kk < 8; kk++) {
            const float y2 = zc - w1[kk];
            const float maha = fmaf(y2, y2, m01[kk]);
            const float p = __expf(-0.5f * maha);
            sum += p;
            sv[idx] = p;
            idx += THREADS;
        }
    }

    // ---------------- Phase 2: block-wide sum ----------------
    #pragma unroll
    for (int o = 16; o; o >>= 1) sum += __shfl_xor_sync(0xffffffffu, sum, o);
    if (lane == 0) sred[w] = sum;
    __syncthreads();

    float tot = 0.f;
    #pragma unroll
    for (int i = 0; i < 16; i++) tot += sred[i];
    const float inv = __fdividef(1.f, tot + 1e-10f);

    // ---------------- Phase 3: normalize + coalesced float4 store ----------------
    const float4* sv4 = (const float4*)sv;
    float4* out4 = (float4*)(out + (size_t)n * NPIX);
    #pragma unroll
    for (int k = 0; k < 16; k++) {
        const int vv = tid + k * THREADS;     // float4 index, 8192 total
        float4 v = sv4[vv];
        v.x *= inv; v.y *= inv; v.z *= inv; v.w *= inv;
        out4[vv] = v;
    }
}

extern "C" void kernel_launch(void* const* d_in, const int* in_sizes, int n_in,
                              void* d_out, int out_size)
{
    const float* rep = (const float*)d_in[0];   // (1024, 256)
    const float* mW  = (const float*)d_in[1];   // (3, 256)
    const float* mb  = (const float*)d_in[2];   // (3,)
    const float* sW  = (const float*)d_in[3];   // (6, 256)
    const float* sb  = (const float*)d_in[4];   // (6,)
    float* out = (float*)d_out;                 // (1024, 32768)

    cudaFuncSetAttribute(mvnd_kernel,
                         cudaFuncAttributeMaxDynamicSharedMemorySize, SMEM_BYTES);
    mvnd_kernel<<<1024, THREADS, SMEM_BYTES>>>(rep, mW, mb, sW, sb, out);
}